// round 10
// baseline (speedup 1.0000x reference)
#include <cuda_runtime.h>
#include <cuda_bf16.h>
#include <math.h>
#include <stdint.h>

// Problem constants
#define BATCH   8
#define SEQ     4096
#define DIM     1024
#define ROWS    (BATCH * SEQ)         // 32768
#define HEADS   4
#define DHEAD   32
#define HID     128
#define NCHUNK  32
#define EPS     1e-5f
#define SCALE   0.17677669529663688f  // 32^-0.5

#define SWZ(o) ((o) ^ (((o) >> 3) & 0x70))

// ---------------------------------------------------------------------------
// Scratch (static device globals; allocation-free)
// ---------------------------------------------------------------------------
__device__ __align__(256) __nv_bfloat16 g_q[(size_t)ROWS * HID];        // 8 MB
__device__ __align__(256) __nv_bfloat16 g_k[(size_t)ROWS * HID];        // 8 MB
__device__ __align__(256) __nv_bfloat16 g_v[(size_t)ROWS * HID];        // 8 MB
__device__ __align__(256) __nv_bfloat16 g_oa[(size_t)ROWS * HID];       // 8 MB
__device__ __align__(256) __nv_bfloat16 g_wqkvT[384 * DIM];             // [n][k], gamma folded
__device__ __align__(256) __nv_bfloat16 g_woutT[DIM * HID];             // [n][k]
__device__ float g_c1[384];   // sum_k gamma_k * W[k][n]
__device__ float g_c2[384];   // sum_k beta_k  * W[k][n]
__device__ float g_pctx[NCHUNK * BATCH * HEADS * DHEAD * DHEAD];
__device__ float g_pS[NCHUNK * BATCH * HID];
__device__ float g_ctx[BATCH * HEADS * DHEAD * DHEAD];

// ---------------------------------------------------------------------------
// PTX helpers (sm_80-era, compile for plain compute_103)
// ---------------------------------------------------------------------------
__device__ __forceinline__ uint32_t smem_to_u32(const void* p) {
    uint32_t a;
    asm("{ .reg .u64 t; cvta.to.shared.u64 t, %1; cvt.u32.u64 %0, t; }"
        : "=r"(a) : "l"(p));
    return a;
}
__device__ __forceinline__ void cp_async16(uint32_t dst, const void* src) {
    asm volatile("cp.async.cg.shared.global [%0], [%1], 16;" :: "r"(dst), "l"(src));
}
__device__ __forceinline__ void cp_commit() {
    asm volatile("cp.async.commit_group;" ::: "memory");
}
__device__ __forceinline__ void cp_wait1() {
    asm volatile("cp.async.wait_group 1;" ::: "memory");
}
__device__ __forceinline__ void cp_wait0() {
    asm volatile("cp.async.wait_group 0;" ::: "memory");
}
__device__ __forceinline__ void ldsm_x4(uint32_t& r0, uint32_t& r1,
                                        uint32_t& r2, uint32_t& r3, uint32_t a) {
    asm volatile("ldmatrix.sync.aligned.m8n8.x4.shared.b16 {%0,%1,%2,%3}, [%4];"
        : "=r"(r0), "=r"(r1), "=r"(r2), "=r"(r3) : "r"(a));
}
__device__ __forceinline__ void mma16816(float* d, const uint32_t* a, const uint32_t* b) {
    asm volatile("mma.sync.aligned.m16n8k16.row.col.f32.bf16.bf16.f32 "
        "{%0,%1,%2,%3}, {%4,%5,%6,%7}, {%8,%9}, {%0,%1,%2,%3};"
        : "+f"(d[0]), "+f"(d[1]), "+f"(d[2]), "+f"(d[3])
        : "r"(a[0]), "r"(a[1]), "r"(a[2]), "r"(a[3]), "r"(b[0]), "r"(b[1]));
}

// ---------------------------------------------------------------------------
// K_QKV fused: LN + GEMM.
//   qkv[m,n] = r_m*(G[m,n] - mu_m*c1[n]) + c2[n],  G = x @ (gamma.*W)
// Reads raw fp32 x via cp.async -> stage, converts to bf16 A tiles in smem,
// accumulates per-row sum/sumsq during conversion (stats on idle pipes).
// grid (3, 256), 256 threads, occ 2, smem 99328 B.
// ---------------------------------------------------------------------------
#define QF_ABF   0u          // 2 x 16384 bf16 A tiles
#define QF_BBF   32768u      // 2 x 16384 bf16 B tiles
#define QF_STG   65536u      // 32768 fp32 x stage
#define QF_STAT  98304u      // mu[128], rs[128]
#define QF_SMEM  99328

__global__ __launch_bounds__(256, 2) void k_qkv_fused(const float* __restrict__ x) {
    extern __shared__ __align__(1024) char smem[];
    const uint32_t sb = smem_to_u32(smem);
    const int tid = threadIdx.x, lane = tid & 31, wid = tid >> 5;
    const int wm = wid & 3, wn = wid >> 2;
    const int rowg0 = blockIdx.y * 128;
    const int ncol0 = blockIdx.x * 128;

    float acc[2][8][4];
    #pragma unroll
    for (int mt = 0; mt < 2; ++mt)
        #pragma unroll
        for (int nt = 0; nt < 8; ++nt)
            #pragma unroll
            for (int i = 0; i < 4; ++i) acc[mt][nt][i] = 0.f;
    float ssum[8], sqs[8];
    #pragma unroll
    for (int p = 0; p < 8; ++p) { ssum[p] = 0.f; sqs[p] = 0.f; }

    const int lr8 = tid >> 3, lc8 = tid & 7;

    auto loadB = [&](int it, int stage) {
        const __nv_bfloat16* Bs = g_wqkvT + (size_t)ncol0 * DIM + it * 64;
        #pragma unroll
        for (int p = 0; p < 4; ++p) {
            const int r = lr8 + p * 32;
            cp_async16(sb + QF_BBF + (uint32_t)stage * 16384u
                           + SWZ((uint32_t)(r * 128 + lc8 * 16)),
                       Bs + (size_t)r * DIM + lc8 * 8);
        }
    };
    auto loadA = [&](int it) {
        // fp32 x tile [128 rows][64 cols] = 2048 x 16B chunks, linear layout
        #pragma unroll
        for (int p = 0; p < 8; ++p) {
            const int f = tid + p * 256;
            const int r = f >> 4, c16 = f & 15;
            cp_async16(sb + QF_STG + (uint32_t)f * 16u,
                       x + (size_t)(rowg0 + r) * DIM + it * 64 + c16 * 4);
        }
    };

    loadA(0); loadB(0, 0); cp_commit();

    const int a_row = ((lane >> 3) & 1) * 8 + (lane & 7);
    const int a_kh  = (lane >> 4) * 8;
    const int b_nr  = (lane >> 4) * 8 + (lane & 7);
    const int b_kh  = ((lane >> 3) & 1) * 8;

    for (int it = 0; it < 16; ++it) {
        cp_wait0();
        __syncthreads();            // stage + B tile visible to all
        // convert stage fp32 -> Abf[it&1] bf16 (SW128), accumulate stats.
        // Thread t handles float4 idx f = t + 256p -> fixed rows (t>>4)+16p.
        const uint32_t Ab = QF_ABF + (uint32_t)(it & 1) * 16384u;
        #pragma unroll
        for (int p = 0; p < 8; ++p) {
            const int f = tid + p * 256;
            const float4 v = *((const float4*)(smem + QF_STG) + f);
            ssum[p] += v.x + v.y + v.z + v.w;
            sqs[p] = fmaf(v.x, v.x, fmaf(v.y, v.y,
                      fmaf(v.z, v.z, fmaf(v.w, v.w, sqs[p]))));
            const int r = f >> 4, c4 = f & 15;
            __nv_bfloat162 b0 = __float22bfloat162_rn(make_float2(v.x, v.y));
            __nv_bfloat162 b1 = __float22bfloat162_rn(make_float2(v.z, v.w));
            uint2 pk;
            pk.x = *(uint32_t*)&b0;
            pk.y = *(uint32_t*)&b1;
            *(uint2*)(smem + Ab + SWZ((uint32_t)(r * 128 + c4 * 8))) = pk;
        }
        __syncthreads();            // stage free, Abf ready
        if (it + 1 < 16) { loadA(it + 1); loadB(it + 1, (it + 1) & 1); cp_commit(); }

        const uint32_t Ao = sb + Ab;
        const uint32_t Bo = sb + QF_BBF + (uint32_t)(it & 1) * 16384u;
        #pragma unroll
        for (int ks = 0; ks < 4; ++ks) {
            uint32_t a[2][4];
            #pragma unroll
            for (int mt = 0; mt < 2; ++mt) {
                const int row = wm * 32 + mt * 16 + a_row;
                const int kc  = ks * 16 + a_kh;
                ldsm_x4(a[mt][0], a[mt][1], a[mt][2], a[mt][3],
                        Ao + SWZ((uint32_t)(row * 128 + kc * 2)));
            }
            uint32_t b[8][2];
            #pragma unroll
            for (int np = 0; np < 4; ++np) {
                const int nr = wn * 64 + np * 16 + b_nr;
                const int kc = ks * 16 + b_kh;
                ldsm_x4(b[np * 2][0], b[np * 2][1], b[np * 2 + 1][0], b[np * 2 + 1][1],
                        Bo + SWZ((uint32_t)(nr * 128 + kc * 2)));
            }
            #pragma unroll
            for (int mt = 0; mt < 2; ++mt)
                #pragma unroll
                for (int nt = 0; nt < 8; ++nt)
                    mma16816(acc[mt][nt], a[mt], b[nt]);
        }
    }

    // per-row LN stats: reduce across the 16 lanes sharing each row class
    #pragma unroll
    for (int m = 1; m <= 8; m <<= 1)
        #pragma unroll
        for (int p = 0; p < 8; ++p) {
            ssum[p] += __shfl_xor_sync(0xffffffffu, ssum[p], m);
            sqs[p]  += __shfl_xor_sync(0xffffffffu, sqs[p],  m);
        }
    float* mu = (float*)(smem + QF_STAT);
    float* rs = (float*)(smem + QF_STAT + 512);
    if ((lane & 15) == 0) {
        #pragma unroll
        for (int p = 0; p < 8; ++p) {
            const int r = wid * 2 + (lane >> 4) + 16 * p;
            const float m_ = ssum[p] * (1.0f / DIM);
            const float v_ = sqs[p] * (1.0f / DIM) - m_ * m_;
            mu[r] = m_;
            rs[r] = rsqrtf(v_ + EPS);
        }
    }
    __syncthreads();

    // epilogue: qkv = rs*(acc - mu*c1) + c2 -> bf16 split q/k/v
    __nv_bfloat16* dst = (blockIdx.x == 0) ? g_q : (blockIdx.x == 1) ? g_k : g_v;
    #pragma unroll
    for (int mt = 0; mt < 2; ++mt) {
        const int lr0 = wm * 32 + mt * 16 + (lane >> 2);
        const float m0 = mu[lr0],     r0v = rs[lr0];
        const float m1 = mu[lr0 + 8], r1v = rs[lr0 + 8];
        #pragma unroll
        for (int nt = 0; nt < 8; ++nt) {
            const int c = wn * 64 + nt * 8 + (lane & 3) * 2;
            const float2 c1v = *(const float2*)(g_c1 + ncol0 + c);
            const float2 c2v = *(const float2*)(g_c2 + ncol0 + c);
            float o00 = r0v * (acc[mt][nt][0] - m0 * c1v.x) + c2v.x;
            float o01 = r0v * (acc[mt][nt][1] - m0 * c1v.y) + c2v.y;
            float o10 = r1v * (acc[mt][nt][2] - m1 * c1v.x) + c2v.x;
            float o11 = r1v * (acc[mt][nt][3] - m1 * c1v.y) + c2v.y;
            *(__nv_bfloat162*)(dst + (size_t)(rowg0 + lr0) * HID + c) =
                __float22bfloat162_rn(make_float2(o00, o01));
            *(__nv_bfloat162*)(dst + (size_t)(rowg0 + lr0 + 8) * HID + c) =
                __float22bfloat162_rn(make_float2(o10, o11));
        }
    }
}

// ---------------------------------------------------------------------------
// out GEMM (R6 2-stage config): out = oa @ woutT^T + b_out + x
// ---------------------------------------------------------------------------
template<int LDA, int LDB, int KITERS>
__device__ __forceinline__ void gemm_out_body(const __nv_bfloat16* __restrict__ A,
                                              const __nv_bfloat16* __restrict__ B,
                                              float* __restrict__ C,
                                              const float* __restrict__ bias,
                                              const float* __restrict__ xres,
                                              char* smem) {
    const uint32_t sb = smem_to_u32(smem);
    const int tid = threadIdx.x;
    const int lane = tid & 31, wid = tid >> 5;
    const int wm = wid & 3, wn = wid >> 2;
    const int rowg0 = blockIdx.y * 128;
    const int ncol0 = blockIdx.x * 128;

    const int lr = tid >> 3, lc = tid & 7;

    float acc[2][8][4];
    #pragma unroll
    for (int mt = 0; mt < 2; ++mt)
        #pragma unroll
        for (int nt = 0; nt < 8; ++nt)
            #pragma unroll
            for (int i = 0; i < 4; ++i) acc[mt][nt][i] = 0.f;

    auto load_stage = [&](int it, int stage) {
        const uint32_t Ao = (uint32_t)stage * 32768u;
        const uint32_t Bo = Ao + 16384u;
        const __nv_bfloat16* As = A + (size_t)rowg0 * LDA + it * 64;
        const __nv_bfloat16* Bs = B + (size_t)ncol0 * LDB + it * 64;
        #pragma unroll
        for (int p = 0; p < 4; ++p) {
            const int r = lr + p * 32;
            cp_async16(sb + Ao + SWZ((uint32_t)(r * 128 + lc * 16)),
                       As + (size_t)r * LDA + lc * 8);
        }
        #pragma unroll
        for (int p = 0; p < 4; ++p) {
            const int r = lr + p * 32;
            cp_async16(sb + Bo + SWZ((uint32_t)(r * 128 + lc * 16)),
                       Bs + (size_t)r * LDB + lc * 8);
        }
        cp_commit();
    };

    load_stage(0, 0);

    const int a_row = ((lane >> 3) & 1) * 8 + (lane & 7);
    const int a_kh  = (lane >> 4) * 8;
    const int b_nr  = (lane >> 4) * 8 + (lane & 7);
    const int b_kh  = ((lane >> 3) & 1) * 8;

    for (int it = 0; it < KITERS; ++it) {
        if (it + 1 < KITERS) load_stage(it + 1, (it + 1) & 1);
        else cp_commit();
        cp_wait1();
        __syncthreads();

        const uint32_t Ao = sb + (uint32_t)(it & 1) * 32768u;
        const uint32_t Bo = Ao + 16384u;

        #pragma unroll
        for (int ks = 0; ks < 4; ++ks) {
            uint32_t a[2][4];
            #pragma unroll
            for (int mt = 0; mt < 2; ++mt) {
                const int row = wm * 32 + mt * 16 + a_row;
                const int kc  = ks * 16 + a_kh;
                ldsm_x4(a[mt][0], a[mt][1], a[mt][2], a[mt][3],
                        Ao + SWZ((uint32_t)(row * 128 + kc * 2)));
            }
            uint32_t b[8][2];
            #pragma unroll
            for (int np = 0; np < 4; ++np) {
                const int nr = wn * 64 + np * 16 + b_nr;
                const int kc = ks * 16 + b_kh;
                ldsm_x4(b[np * 2][0], b[np * 2][1], b[np * 2 + 1][0], b[np * 2 + 1][1],
                        Bo + SWZ((uint32_t)(nr * 128 + kc * 2)));
            }
            #pragma unroll
            for (int mt = 0; mt < 2; ++mt)
                #pragma unroll
                for (int nt = 0; nt < 8; ++nt)
                    mma16816(acc[mt][nt], a[mt], b[nt]);
        }
        __syncthreads();
    }

    #pragma unroll
    for (int mt = 0; mt < 2; ++mt) {
        const int r0 = rowg0 + wm * 32 + mt * 16 + (lane >> 2);
        #pragma unroll
        for (int nt = 0; nt < 8; ++nt) {
            const int c = ncol0 + wn * 64 + nt * 8 + (lane & 3) * 2;
            float2 v0 = make_float2(acc[mt][nt][0], acc[mt][nt][1]);
            float2 v1 = make_float2(acc[mt][nt][2], acc[mt][nt][3]);
            const float2 bo = *(const float2*)(bias + c);
            const float2 x0 = *(const float2*)(xres + (size_t)r0 * DIM + c);
            const float2 x1 = *(const float2*)(xres + (size_t)(r0 + 8) * DIM + c);
            v0.x += bo.x + x0.x; v0.y += bo.y + x0.y;
            v1.x += bo.x + x1.x; v1.y += bo.y + x1.y;
            *(float2*)(C + (size_t)r0 * DIM + c) = v0;
            *(float2*)(C + (size_t)(r0 + 8) * DIM + c) = v1;
        }
    }
}

#define GEMM_SMEM 65536

__global__ __launch_bounds__(256, 2) void k_out_mma(const float* __restrict__ x,
                                                    const float* __restrict__ b_out,
                                                    float* __restrict__ out) {
    extern __shared__ __align__(1024) char smem[];
    gemm_out_body<HID, HID, 2>(g_oa, g_woutT, out, b_out, x, smem);
}

// ---------------------------------------------------------------------------
// K0: weight prep (transpose + bf16; gamma folded into wqkvT)
// ---------------------------------------------------------------------------
__global__ __launch_bounds__(256) void k_prep(const float* __restrict__ wqkv,
                                              const float* __restrict__ wout,
                                              const float* __restrict__ gamma) {
    const int idx = blockIdx.x * 256 + threadIdx.x;
    if (idx < 384 * DIM) {
        const int n = idx >> 10, k = idx & 1023;
        g_wqkvT[idx] = __float2bfloat16(wqkv[k * 384 + n] * gamma[k]);
    }
    if (idx < DIM * HID) {
        const int n = idx >> 7, k = idx & 127;
        g_woutT[idx] = __float2bfloat16(wout[k * DIM + n]);
    }
}

// c1[n] = sum_k gamma_k W[k][n], c2[n] = sum_k beta_k W[k][n]
__global__ __launch_bounds__(192) void k_prepc(const float* __restrict__ wqkv,
                                               const float* __restrict__ gamma,
                                               const float* __restrict__ beta) {
    const int n = blockIdx.x * 192 + threadIdx.x;
    if (n >= 384) return;
    float s1 = 0.f, s2 = 0.f;
    for (int k = 0; k < DIM; ++k) {
        const float w = wqkv[k * 384 + n];
        s1 = fmaf(gamma[k], w, s1);
        s2 = fmaf(beta[k],  w, s2);
    }
    g_c1[n] = s1;
    g_c2[n] = s2;
}

// ---------------------------------------------------------------------------
// K3: per-chunk partials of exp(k)*v and column-sums of exp(k)  (bf16 inputs)
// ---------------------------------------------------------------------------
__global__ __launch_bounds__(256) void k_ctx_part() {
    const int chunk = blockIdx.x, h = blockIdx.y, b = blockIdx.z;
    const int tid = threadIdx.x;

    __shared__ __align__(16) float ks[128][32];
    __shared__ __align__(16) float vs[128][32];

    const int rbase = b * SEQ + chunk * 128;
    #pragma unroll
    for (int p = 0; p < 2; ++p) {
        const int idx = tid + p * 256;
        const int r = idx >> 2, c4 = idx & 3;
        const size_t off = (size_t)(rbase + r) * HID + h * DHEAD + c4 * 8;
        const uint4 kq = *(const uint4*)(g_k + off);
        const uint4 vq = *(const uint4*)(g_v + off);
        const uint32_t kw[4] = {kq.x, kq.y, kq.z, kq.w};
        const uint32_t vw[4] = {vq.x, vq.y, vq.z, vq.w};
        #pragma unroll
        for (int i = 0; i < 4; ++i) {
            const float2 kf = __bfloat1622float2(*(const __nv_bfloat162*)&kw[i]);
            const float2 vf = __bfloat1622float2(*(const __nv_bfloat162*)&vw[i]);
            ks[r][c4 * 8 + i * 2 + 0] = __expf(kf.x);
            ks[r][c4 * 8 + i * 2 + 1] = __expf(kf.y);
            vs[r][c4 * 8 + i * 2 + 0] = vf.x;
            vs[r][c4 * 8 + i * 2 + 1] = vf.y;
        }
    }
    __syncthreads();

    if (tid < 32) {
        float s = 0.f;
        #pragma unroll
        for (int r = 0; r < 128; ++r) s += ks[r][tid];
        g_pS[chunk * (BATCH * HID) + b * HID + h * DHEAD + tid] = s;
    }

    const int e  = tid & 31;
    const int d4 = tid >> 5;
    float acc[4] = {0.f, 0.f, 0.f, 0.f};
    #pragma unroll 4
    for (int r = 0; r < 128; ++r) {
        const float4 kk = *(const float4*)&ks[r][d4 * 4];
        const float ve = vs[r][e];
        acc[0] = fmaf(kk.x, ve, acc[0]);
        acc[1] = fmaf(kk.y, ve, acc[1]);
        acc[2] = fmaf(kk.z, ve, acc[2]);
        acc[3] = fmaf(kk.w, ve, acc[3]);
    }
    const size_t ob = (size_t)chunk * 32768 + (size_t)b * 4096 + (size_t)h * 1024;
    #pragma unroll
    for (int i = 0; i < 4; ++i)
        g_pctx[ob + (size_t)(d4 * 4 + i) * 32 + e] = acc[i];
}

// ---------------------------------------------------------------------------
// K4: reduce partials (grid 128 x 256)
// ---------------------------------------------------------------------------
__global__ __launch_bounds__(256) void k_ctx_reduce() {
    const int o  = blockIdx.x * 256 + threadIdx.x;
    const int bi = o >> 12;
    const int hd = (o >> 5) & 127;
    float s = 0.f, S = 0.f;
    #pragma unroll
    for (int c = 0; c < NCHUNK; ++c) {
        s += g_pctx[(size_t)c * 32768 + o];
        S += g_pS[c * (BATCH * HID) + bi * HID + hd];
    }
    g_ctx[o] = s * SCALE / S;
}

// ---------------------------------------------------------------------------
// K5: oa = q @ ctx -> bf16
// ---------------------------------------------------------------------------
__global__ __launch_bounds__(256, 2) void k_oa() {
    extern __shared__ char smem[];
    float* ctxs = (float*)smem;              // 16 KB
    float* qs   = (float*)(smem + 16384);    // 64 KB

    const int tid = threadIdx.x;
    const size_t rowg0 = (size_t)blockIdx.x * 128;
    const int bi = (int)(rowg0 >> 12);

    #pragma unroll
    for (int i = 0; i < 16; ++i)
        ctxs[i * 256 + tid] = g_ctx[bi * 4096 + i * 256 + tid];
    #pragma unroll
    for (int p = 0; p < 8; ++p) {
        const int idx = tid + p * 256;
        const int r = idx >> 4, c8 = idx & 15;
        const uint4 qv = *(const uint4*)(g_q + (rowg0 + r) * HID + c8 * 8);
        const uint32_t qw[4] = {qv.x, qv.y, qv.z, qv.w};
        #pragma unroll
        for (int i = 0; i < 4; ++i) {
            const float2 f = __bfloat1622float2(*(const __nv_bfloat162*)&qw[i]);
            qs[r * 128 + c8 * 8 + i * 2 + 0] = f.x;
            qs[r * 128 + c8 * 8 + i * 2 + 1] = f.y;
        }
    }
    __syncthreads();

    const int col = tid & 127, rh = tid >> 7;
    const int h = col >> 5, e = col & 31;
    float cv[32];
    #pragma unroll
    for (int d = 0; d < 32; ++d) cv[d] = ctxs[h * 1024 + d * 32 + e];

    for (int rr = 0; rr < 64; ++rr) {
        const int r = rh * 64 + rr;
        const float* qrow = qs + r * 128 + h * 32;
        float a = 0.f;
        #pragma unroll
        for (int d = 0; d < 32; ++d) a = fmaf(qrow[d], cv[d], a);
        g_oa[(rowg0 + r) * HID + col] = __float2bfloat16(a);
    }
}

// ---------------------------------------------------------------------------
extern "C" void kernel_launch(void* const* d_in, const int* in_sizes, int n_in,
                              void* d_out, int out_size) {
    const float* x     = (const float*)d_in[0];
    const float* gamma = (const float*)d_in[1];
    const float* beta  = (const float*)d_in[2];
    const float* wqkv  = (const float*)d_in[3];
    const float* wout  = (const float*)d_in[4];
    const float* bout  = (const float*)d_in[5];
    float* out = (float*)d_out;

    cudaFuncSetAttribute(k_qkv_fused, cudaFuncAttributeMaxDynamicSharedMemorySize, QF_SMEM);
    cudaFuncSetAttribute(k_out_mma,   cudaFuncAttributeMaxDynamicSharedMemorySize, GEMM_SMEM);
    cudaFuncSetAttribute(k_oa,        cudaFuncAttributeMaxDynamicSharedMemorySize, 81920);

    k_prep<<<1536, 256>>>(wqkv, wout, gamma);
    k_prepc<<<2, 192>>>(wqkv, gamma, beta);
    k_qkv_fused<<<dim3(3, 256), 256, QF_SMEM>>>(x);
    k_ctx_part<<<dim3(NCHUNK, HEADS, BATCH), 256>>>();
    k_ctx_reduce<<<128, 256>>>();
    k_oa<<<256, 256, 81920>>>();
    k_out_mma<<<dim3(8, 256), 256, GEMM_SMEM>>>(x, bout, out);
}

// round 11
// speedup vs baseline: 1.2075x; 1.2075x over previous
#include <cuda_runtime.h>
#include <cuda_bf16.h>
#include <math.h>
#include <stdint.h>

// Problem constants
#define BATCH   8
#define SEQ     4096
#define DIM     1024
#define ROWS    (BATCH * SEQ)         // 32768
#define HEADS   4
#define DHEAD   32
#define HID     128
#define NCHUNK  32
#define EPS     1e-5f
#define SCALE   0.17677669529663688f  // 32^-0.5

#define SWZ(o) ((o) ^ (((o) >> 3) & 0x70))

// ---------------------------------------------------------------------------
// Scratch (static device globals; allocation-free)
// ---------------------------------------------------------------------------
__device__ __align__(256) __nv_bfloat16 g_xn[(size_t)ROWS * DIM];       // 64 MB
__device__ __align__(256) __nv_bfloat16 g_q[(size_t)ROWS * HID];        // 8 MB
__device__ __align__(256) __nv_bfloat16 g_k[(size_t)ROWS * HID];        // 8 MB
__device__ __align__(256) __nv_bfloat16 g_v[(size_t)ROWS * HID];        // 8 MB
__device__ __align__(256) __nv_bfloat16 g_wqkvT[384 * DIM];             // [n][k]
__device__ __align__(256) __nv_bfloat16 g_wbT[BATCH * DIM * HID];       // [b][c][j], 2 MB
__device__ float g_pctx[NCHUNK * BATCH * HEADS * DHEAD * DHEAD];
__device__ float g_pS[NCHUNK * BATCH * HID];
__device__ float g_ctx[BATCH * HEADS * DHEAD * DHEAD];

// ---------------------------------------------------------------------------
// PTX helpers (sm_80-era, compile for plain compute_103)
// ---------------------------------------------------------------------------
__device__ __forceinline__ uint32_t smem_to_u32(const void* p) {
    uint32_t a;
    asm("{ .reg .u64 t; cvta.to.shared.u64 t, %1; cvt.u32.u64 %0, t; }"
        : "=r"(a) : "l"(p));
    return a;
}
__device__ __forceinline__ void cp_async16(uint32_t dst, const void* src) {
    asm volatile("cp.async.cg.shared.global [%0], [%1], 16;" :: "r"(dst), "l"(src));
}
__device__ __forceinline__ void cp_commit() {
    asm volatile("cp.async.commit_group;" ::: "memory");
}
__device__ __forceinline__ void cp_wait1() {
    asm volatile("cp.async.wait_group 1;" ::: "memory");
}
__device__ __forceinline__ void ldsm_x4(uint32_t& r0, uint32_t& r1,
                                        uint32_t& r2, uint32_t& r3, uint32_t a) {
    asm volatile("ldmatrix.sync.aligned.m8n8.x4.shared.b16 {%0,%1,%2,%3}, [%4];"
        : "=r"(r0), "=r"(r1), "=r"(r2), "=r"(r3) : "r"(a));
}
__device__ __forceinline__ void mma16816(float* d, const uint32_t* a, const uint32_t* b) {
    asm volatile("mma.sync.aligned.m16n8k16.row.col.f32.bf16.bf16.f32 "
        "{%0,%1,%2,%3}, {%4,%5,%6,%7}, {%8,%9}, {%0,%1,%2,%3};"
        : "+f"(d[0]), "+f"(d[1]), "+f"(d[2]), "+f"(d[3])
        : "r"(a[0]), "r"(a[1]), "r"(a[2]), "r"(a[3]), "r"(b[0]), "r"(b[1]));
}

// ---------------------------------------------------------------------------
// Generic HMMA GEMM body (R6 2-stage config — measured best).
// C[M,N] = A[M,K](bf16,row) @ B[N,K](bf16,K-major)^T
// Block tile 128x128, BK=64, 256 threads (8 warps of 32x64), 2-stage cp.async.
// OUT_EPI=false: store bf16 to g_q/g_k/g_v selected by blockIdx.x.
// OUT_EPI=true:  store fp32 + bias + residual x.
// ---------------------------------------------------------------------------
template<int LDA, int LDB, int KITERS, bool OUT_EPI>
__device__ __forceinline__ void gemm_body(const __nv_bfloat16* __restrict__ A,
                                          const __nv_bfloat16* __restrict__ B,
                                          float* __restrict__ C,
                                          const float* __restrict__ bias,
                                          const float* __restrict__ xres,
                                          char* smem) {
    const uint32_t sb = smem_to_u32(smem);
    const int tid = threadIdx.x;
    const int lane = tid & 31, wid = tid >> 5;
    const int wm = wid & 3, wn = wid >> 2;
    const int rowg0 = blockIdx.y * 128;
    const int ncol0 = blockIdx.x * 128;

    const int lr = tid >> 3, lc = tid & 7;   // stage-fill indexing

    float acc[2][8][4];
    #pragma unroll
    for (int mt = 0; mt < 2; ++mt)
        #pragma unroll
        for (int nt = 0; nt < 8; ++nt)
            #pragma unroll
            for (int i = 0; i < 4; ++i) acc[mt][nt][i] = 0.f;

    auto load_stage = [&](int it, int stage) {
        const uint32_t Ao = (uint32_t)stage * 32768u;
        const uint32_t Bo = Ao + 16384u;
        const __nv_bfloat16* As = A + (size_t)rowg0 * LDA + it * 64;
        const __nv_bfloat16* Bs = B + (size_t)ncol0 * LDB + it * 64;
        #pragma unroll
        for (int p = 0; p < 4; ++p) {
            const int r = lr + p * 32;
            cp_async16(sb + Ao + SWZ((uint32_t)(r * 128 + lc * 16)),
                       As + (size_t)r * LDA + lc * 8);
        }
        #pragma unroll
        for (int p = 0; p < 4; ++p) {
            const int r = lr + p * 32;
            cp_async16(sb + Bo + SWZ((uint32_t)(r * 128 + lc * 16)),
                       Bs + (size_t)r * LDB + lc * 8);
        }
        cp_commit();
    };

    load_stage(0, 0);

    // precomputed ldmatrix lane offsets
    const int a_row = ((lane >> 3) & 1) * 8 + (lane & 7);
    const int a_kh  = (lane >> 4) * 8;
    const int b_nr  = (lane >> 4) * 8 + (lane & 7);
    const int b_kh  = ((lane >> 3) & 1) * 8;

    for (int it = 0; it < KITERS; ++it) {
        if (it + 1 < KITERS) load_stage(it + 1, (it + 1) & 1);
        else cp_commit();                      // keep group accounting uniform
        cp_wait1();
        __syncthreads();

        const uint32_t Ao = sb + (uint32_t)(it & 1) * 32768u;
        const uint32_t Bo = Ao + 16384u;

        #pragma unroll
        for (int ks = 0; ks < 4; ++ks) {
            uint32_t a[2][4];
            #pragma unroll
            for (int mt = 0; mt < 2; ++mt) {
                const int row = wm * 32 + mt * 16 + a_row;
                const int kc  = ks * 16 + a_kh;
                ldsm_x4(a[mt][0], a[mt][1], a[mt][2], a[mt][3],
                        Ao + SWZ((uint32_t)(row * 128 + kc * 2)));
            }
            uint32_t b[8][2];
            #pragma unroll
            for (int np = 0; np < 4; ++np) {
                const int nr = wn * 64 + np * 16 + b_nr;
                const int kc = ks * 16 + b_kh;
                ldsm_x4(b[np * 2][0], b[np * 2][1], b[np * 2 + 1][0], b[np * 2 + 1][1],
                        Bo + SWZ((uint32_t)(nr * 128 + kc * 2)));
            }
            #pragma unroll
            for (int mt = 0; mt < 2; ++mt)
                #pragma unroll
                for (int nt = 0; nt < 8; ++nt)
                    mma16816(acc[mt][nt], a[mt], b[nt]);
        }
        __syncthreads();
    }

    if (OUT_EPI) {
        // fp32 store + bias + residual
        #pragma unroll
        for (int mt = 0; mt < 2; ++mt) {
            const int r0 = rowg0 + wm * 32 + mt * 16 + (lane >> 2);
            #pragma unroll
            for (int nt = 0; nt < 8; ++nt) {
                const int c = ncol0 + wn * 64 + nt * 8 + (lane & 3) * 2;
                float2 v0 = make_float2(acc[mt][nt][0], acc[mt][nt][1]);
                float2 v1 = make_float2(acc[mt][nt][2], acc[mt][nt][3]);
                const float2 bo = *(const float2*)(bias + c);
                const float2 x0 = *(const float2*)(xres + (size_t)r0 * DIM + c);
                const float2 x1 = *(const float2*)(xres + (size_t)(r0 + 8) * DIM + c);
                v0.x += bo.x + x0.x; v0.y += bo.y + x0.y;
                v1.x += bo.x + x1.x; v1.y += bo.y + x1.y;
                *(float2*)(C + (size_t)r0 * DIM + c) = v0;
                *(float2*)(C + (size_t)(r0 + 8) * DIM + c) = v1;
            }
        }
    } else {
        // bf16 store into split q/k/v arrays (row stride HID=128)
        __nv_bfloat16* dst = (blockIdx.x == 0) ? g_q : (blockIdx.x == 1) ? g_k : g_v;
        #pragma unroll
        for (int mt = 0; mt < 2; ++mt) {
            const int r0 = rowg0 + wm * 32 + mt * 16 + (lane >> 2);
            #pragma unroll
            for (int nt = 0; nt < 8; ++nt) {
                const int c = wn * 64 + nt * 8 + (lane & 3) * 2;   // local col 0..127
                *(__nv_bfloat162*)(dst + (size_t)r0 * HID + c) =
                    __float22bfloat162_rn(make_float2(acc[mt][nt][0], acc[mt][nt][1]));
                *(__nv_bfloat162*)(dst + (size_t)(r0 + 8) * HID + c) =
                    __float22bfloat162_rn(make_float2(acc[mt][nt][2], acc[mt][nt][3]));
            }
        }
    }
}

#define GEMM_SMEM 65536   // 2 stages x 32 KB

// grid (3, 256): q/k/v = xn @ wqkvT^T   (2 blocks/SM)
__global__ __launch_bounds__(256, 2) void k_qkv_mma() {
    extern __shared__ __align__(1024) char smem[];
    gemm_body<DIM, DIM, 16, false>(g_xn, g_wqkvT, nullptr, nullptr, nullptr, smem);
}
// grid (8, 256): out = q @ Wb_b^T + b_out + x   (Wb_b = Ctx_b @ w_out, per batch)
__global__ __launch_bounds__(256, 2) void k_out_mma(const float* __restrict__ x,
                                                    const float* __restrict__ b_out,
                                                    float* __restrict__ out) {
    extern __shared__ __align__(1024) char smem[];
    const int batch = blockIdx.y >> 5;     // 32 row-blocks per batch
    gemm_body<HID, HID, 2, true>(g_q, g_wbT + (size_t)batch * DIM * HID,
                                 out, b_out, x, smem);
}

// ---------------------------------------------------------------------------
// K0: weight prep (transpose + bf16)
// ---------------------------------------------------------------------------
__global__ __launch_bounds__(256) void k_prep(const float* __restrict__ wqkv) {
    const int idx = blockIdx.x * 256 + threadIdx.x;
    if (idx < 384 * DIM) {
        const int n = idx >> 10, k = idx & 1023;
        g_wqkvT[idx] = __float2bfloat16(wqkv[k * 384 + n]);
    }
}

// ---------------------------------------------------------------------------
// K1: LayerNorm -> bf16
// ---------------------------------------------------------------------------
__global__ __launch_bounds__(256) void k_ln(const float* __restrict__ x,
                                            const float* __restrict__ gamma,
                                            const float* __restrict__ beta) {
    const int row = blockIdx.x;
    const int tid = threadIdx.x;
    const float4 f = ((const float4*)(x + (size_t)row * DIM))[tid];

    float s  = f.x + f.y + f.z + f.w;
    float s2 = fmaf(f.x, f.x, fmaf(f.y, f.y, fmaf(f.z, f.z, f.w * f.w)));
    #pragma unroll
    for (int off = 16; off > 0; off >>= 1) {
        s  += __shfl_xor_sync(0xffffffffu, s,  off);
        s2 += __shfl_xor_sync(0xffffffffu, s2, off);
    }
    __shared__ float red[16];
    const int wid = tid >> 5, lane = tid & 31;
    if (lane == 0) { red[wid] = s; red[8 + wid] = s2; }
    __syncthreads();
    float ts = 0.f, ts2 = 0.f;
    #pragma unroll
    for (int w = 0; w < 8; ++w) { ts += red[w]; ts2 += red[8 + w]; }

    const float mean = ts * (1.0f / DIM);
    const float var  = ts2 * (1.0f / DIM) - mean * mean;
    const float rstd = rsqrtf(var + EPS);

    const float4 g  = ((const float4*)gamma)[tid];
    const float4 be = ((const float4*)beta)[tid];
    __nv_bfloat162 p0, p1;
    p0.x = __float2bfloat16((f.x - mean) * rstd * g.x + be.x);
    p0.y = __float2bfloat16((f.y - mean) * rstd * g.y + be.y);
    p1.x = __float2bfloat16((f.z - mean) * rstd * g.z + be.z);
    p1.y = __float2bfloat16((f.w - mean) * rstd * g.w + be.w);
    __nv_bfloat162* o = (__nv_bfloat162*)(g_xn + (size_t)row * DIM);
    o[tid * 2 + 0] = p0;
    o[tid * 2 + 1] = p1;
}

// ---------------------------------------------------------------------------
// K3: per-chunk partials of exp(k)*v and column-sums of exp(k)  (bf16 inputs)
// ---------------------------------------------------------------------------
__global__ __launch_bounds__(256) void k_ctx_part() {
    const int chunk = blockIdx.x, h = blockIdx.y, b = blockIdx.z;
    const int tid = threadIdx.x;

    __shared__ __align__(16) float ks[128][32];
    __shared__ __align__(16) float vs[128][32];

    const int rbase = b * SEQ + chunk * 128;
    #pragma unroll
    for (int p = 0; p < 2; ++p) {
        const int idx = tid + p * 256;
        const int r = idx >> 2, c4 = idx & 3;
        const size_t off = (size_t)(rbase + r) * HID + h * DHEAD + c4 * 8;
        const uint4 kq = *(const uint4*)(g_k + off);
        const uint4 vq = *(const uint4*)(g_v + off);
        const uint32_t kw[4] = {kq.x, kq.y, kq.z, kq.w};
        const uint32_t vw[4] = {vq.x, vq.y, vq.z, vq.w};
        #pragma unroll
        for (int i = 0; i < 4; ++i) {
            const float2 kf = __bfloat1622float2(*(const __nv_bfloat162*)&kw[i]);
            const float2 vf = __bfloat1622float2(*(const __nv_bfloat162*)&vw[i]);
            ks[r][c4 * 8 + i * 2 + 0] = __expf(kf.x);
            ks[r][c4 * 8 + i * 2 + 1] = __expf(kf.y);
            vs[r][c4 * 8 + i * 2 + 0] = vf.x;
            vs[r][c4 * 8 + i * 2 + 1] = vf.y;
        }
    }
    __syncthreads();

    if (tid < 32) {
        float s = 0.f;
        #pragma unroll
        for (int r = 0; r < 128; ++r) s += ks[r][tid];
        g_pS[chunk * (BATCH * HID) + b * HID + h * DHEAD + tid] = s;
    }

    const int e  = tid & 31;
    const int d4 = tid >> 5;
    float acc[4] = {0.f, 0.f, 0.f, 0.f};
    #pragma unroll 4
    for (int r = 0; r < 128; ++r) {
        const float4 kk = *(const float4*)&ks[r][d4 * 4];
        const float ve = vs[r][e];
        acc[0] = fmaf(kk.x, ve, acc[0]);
        acc[1] = fmaf(kk.y, ve, acc[1]);
        acc[2] = fmaf(kk.z, ve, acc[2]);
        acc[3] = fmaf(kk.w, ve, acc[3]);
    }
    const size_t ob = (size_t)chunk * 32768 + (size_t)b * 4096 + (size_t)h * 1024;
    #pragma unroll
    for (int i = 0; i < 4; ++i)
        g_pctx[ob + (size_t)(d4 * 4 + i) * 32 + e] = acc[i];
}

// ---------------------------------------------------------------------------
// K4: reduce partials (grid 128 x 256)
// ---------------------------------------------------------------------------
__global__ __launch_bounds__(256) void k_ctx_reduce() {
    const int o  = blockIdx.x * 256 + threadIdx.x;
    const int bi = o >> 12;
    const int hd = (o >> 5) & 127;
    float s = 0.f, S = 0.f;
    #pragma unroll
    for (int c = 0; c < NCHUNK; ++c) {
        s += g_pctx[(size_t)c * 32768 + o];
        S += g_pS[c * (BATCH * HID) + bi * HID + hd];
    }
    g_ctx[o] = s * SCALE / S;
}

// ---------------------------------------------------------------------------
// K5: Wb_b = Ctx_b @ w_out  -> bf16 K-major [b][c][j]
// grid 64 = 8 batches x 8 c-blocks of 128, 256 threads.
// Warp layout: j = lane + (wid&3)*32 (h = wid&3 const per warp), cg = tid>>7.
// ctx row (32 e-values) held in registers; w_s reads are warp-broadcast.
// ---------------------------------------------------------------------------
__global__ __launch_bounds__(256) void k_wb(const float* __restrict__ wout) {
    __shared__ float ctx_s[4096];        // 16 KB
    __shared__ float w_s[128][128];      // 64 KB

    const int tid = threadIdx.x, lane = tid & 31;
    const int b = blockIdx.x >> 3;
    const int c0 = (blockIdx.x & 7) * 128;

    #pragma unroll
    for (int i = 0; i < 16; ++i)
        ctx_s[i * 256 + tid] = g_ctx[b * 4096 + i * 256 + tid];
    // w_s[r][c] = wout[r*1024 + c0 + c], 4096 float4 loads
    #pragma unroll
    for (int p = 0; p < 16; ++p) {
        const int idx = tid + p * 256;
        const int r = idx >> 5, c4 = idx & 31;
        *(float4*)&w_s[r][c4 * 4] = *(const float4*)(wout + r * DIM + c0 + c4 * 4);
    }
    __syncthreads();

    const int h = (tid >> 5) & 3;        // warp -> head
    const int j = h * 32 + lane;         // hidden index (d = lane)
    const int cg = tid >> 7;             // 0/1 -> c halves

    float cv[32];
    #pragma unroll
    for (int e = 0; e < 32; ++e) cv[e] = ctx_s[h * 1024 + lane * 32 + e];

    for (int cc = 0; cc < 64; ++cc) {
        const int c = cg * 64 + cc;
        float a = 0.f;
        #pragma unroll
        for (int e = 0; e < 32; ++e)
            a = fmaf(cv[e], w_s[h * 32 + e][c], a);   // w_s: warp-broadcast
        g_wbT[((size_t)b * DIM + c0 + c) * HID + j] = __float2bfloat16(a);
    }
}

// ---------------------------------------------------------------------------
extern "C" void kernel_launch(void* const* d_in, const int* in_sizes, int n_in,
                              void* d_out, int out_size) {
    const float* x     = (const float*)d_in[0];
    const float* gamma = (const float*)d_in[1];
    const float* beta  = (const float*)d_in[2];
    const float* wqkv  = (const float*)d_in[3];
    const float* wout  = (const float*)d_in[4];
    const float* bout  = (const float*)d_in[5];
    float* out = (float*)d_out;

    cudaFuncSetAttribute(k_qkv_mma, cudaFuncAttributeMaxDynamicSharedMemorySize, GEMM_SMEM);
    cudaFuncSetAttribute(k_out_mma, cudaFuncAttributeMaxDynamicSharedMemorySize, GEMM_SMEM);

    k_prep<<<1536, 256>>>(wqkv);
    k_ln<<<ROWS, 256>>>(x, gamma, beta);
    k_qkv_mma<<<dim3(3, 256), 256, GEMM_SMEM>>>();
    k_ctx_part<<<dim3(NCHUNK, HEADS, BATCH), 256>>>();
    k_ctx_reduce<<<128, 256>>>();
    k_wb<<<64, 256>>>(wout);
    k_out_mma<<<dim3(8, 256), 256, GEMM_SMEM>>>(x, bout, out);
}

// round 12
// speedup vs baseline: 1.2883x; 1.0668x over previous
#include <cuda_runtime.h>
#include <cuda_bf16.h>
#include <math.h>
#include <stdint.h>

// Problem constants
#define BATCH   8
#define SEQ     4096
#define DIM     1024
#define ROWS    (BATCH * SEQ)         // 32768
#define HEADS   4
#define DHEAD   32
#define HID     128
#define NCHUNK  32
#define EPS     1e-5f
#define SCALE   0.17677669529663688f  // 32^-0.5

#define SWZ(o)  ((o) ^ (((o) >> 3) & 0x70))    // 128B-row swizzle (GEMM tiles)
#define CSWZ(o) ((o) ^ (((o) >> 4) & 0xF0))    // 256B-row swizzle (ctx tiles)

// ---------------------------------------------------------------------------
// Scratch (static device globals; allocation-free)
// ---------------------------------------------------------------------------
__device__ __align__(256) __nv_bfloat16 g_xn[(size_t)ROWS * DIM];       // 64 MB
__device__ __align__(256) __nv_bfloat16 g_q[(size_t)ROWS * HID];        // 8 MB
__device__ __align__(256) __nv_bfloat16 g_k[(size_t)ROWS * HID];        // 8 MB
__device__ __align__(256) __nv_bfloat16 g_v[(size_t)ROWS * HID];        // 8 MB
__device__ __align__(256) __nv_bfloat16 g_wqkvT[384 * DIM];             // [n][k]
__device__ __align__(256) __nv_bfloat16 g_wbT[BATCH * DIM * HID];       // [b][c][j]
__device__ float g_pctx[NCHUNK * BATCH * HEADS * DHEAD * DHEAD];
__device__ float g_pS[NCHUNK * BATCH * HID];
__device__ float g_ctx[BATCH * HEADS * DHEAD * DHEAD];

// ---------------------------------------------------------------------------
// PTX helpers (sm_80-era, compile for plain compute_103)
// ---------------------------------------------------------------------------
__device__ __forceinline__ uint32_t smem_to_u32(const void* p) {
    uint32_t a;
    asm("{ .reg .u64 t; cvta.to.shared.u64 t, %1; cvt.u32.u64 %0, t; }"
        : "=r"(a) : "l"(p));
    return a;
}
__device__ __forceinline__ void cp_async16(uint32_t dst, const void* src) {
    asm volatile("cp.async.cg.shared.global [%0], [%1], 16;" :: "r"(dst), "l"(src));
}
__device__ __forceinline__ void cp_commit() {
    asm volatile("cp.async.commit_group;" ::: "memory");
}
__device__ __forceinline__ void cp_wait1() {
    asm volatile("cp.async.wait_group 1;" ::: "memory");
}
__device__ __forceinline__ void ldsm_x4(uint32_t& r0, uint32_t& r1,
                                        uint32_t& r2, uint32_t& r3, uint32_t a) {
    asm volatile("ldmatrix.sync.aligned.m8n8.x4.shared.b16 {%0,%1,%2,%3}, [%4];"
        : "=r"(r0), "=r"(r1), "=r"(r2), "=r"(r3) : "r"(a));
}
__device__ __forceinline__ void ldsm_x4_t(uint32_t& r0, uint32_t& r1,
                                          uint32_t& r2, uint32_t& r3, uint32_t a) {
    asm volatile("ldmatrix.sync.aligned.m8n8.x4.trans.shared.b16 {%0,%1,%2,%3}, [%4];"
        : "=r"(r0), "=r"(r1), "=r"(r2), "=r"(r3) : "r"(a));
}
__device__ __forceinline__ void mma16816(float* d, const uint32_t* a, const uint32_t* b) {
    asm volatile("mma.sync.aligned.m16n8k16.row.col.f32.bf16.bf16.f32 "
        "{%0,%1,%2,%3}, {%4,%5,%6,%7}, {%8,%9}, {%0,%1,%2,%3};"
        : "+f"(d[0]), "+f"(d[1]), "+f"(d[2]), "+f"(d[3])
        : "r"(a[0]), "r"(a[1]), "r"(a[2]), "r"(a[3]), "r"(b[0]), "r"(b[1]));
}

// ---------------------------------------------------------------------------
// Generic HMMA GEMM body (R6 2-stage config — measured best).
// C[M,N] = A[M,K](bf16,row) @ B[N,K](bf16,K-major)^T
// ---------------------------------------------------------------------------
template<int LDA, int LDB, int KITERS, bool OUT_EPI>
__device__ __forceinline__ void gemm_body(const __nv_bfloat16* __restrict__ A,
                                          const __nv_bfloat16* __restrict__ B,
                                          float* __restrict__ C,
                                          const float* __restrict__ bias,
                                          const float* __restrict__ xres,
                                          char* smem) {
    const uint32_t sb = smem_to_u32(smem);
    const int tid = threadIdx.x;
    const int lane = tid & 31, wid = tid >> 5;
    const int wm = wid & 3, wn = wid >> 2;
    const int rowg0 = blockIdx.y * 128;
    const int ncol0 = blockIdx.x * 128;

    const int lr = tid >> 3, lc = tid & 7;

    float acc[2][8][4];
    #pragma unroll
    for (int mt = 0; mt < 2; ++mt)
        #pragma unroll
        for (int nt = 0; nt < 8; ++nt)
            #pragma unroll
            for (int i = 0; i < 4; ++i) acc[mt][nt][i] = 0.f;

    auto load_stage = [&](int it, int stage) {
        const uint32_t Ao = (uint32_t)stage * 32768u;
        const uint32_t Bo = Ao + 16384u;
        const __nv_bfloat16* As = A + (size_t)rowg0 * LDA + it * 64;
        const __nv_bfloat16* Bs = B + (size_t)ncol0 * LDB + it * 64;
        #pragma unroll
        for (int p = 0; p < 4; ++p) {
            const int r = lr + p * 32;
            cp_async16(sb + Ao + SWZ((uint32_t)(r * 128 + lc * 16)),
                       As + (size_t)r * LDA + lc * 8);
        }
        #pragma unroll
        for (int p = 0; p < 4; ++p) {
            const int r = lr + p * 32;
            cp_async16(sb + Bo + SWZ((uint32_t)(r * 128 + lc * 16)),
                       Bs + (size_t)r * LDB + lc * 8);
        }
        cp_commit();
    };

    load_stage(0, 0);

    const int a_row = ((lane >> 3) & 1) * 8 + (lane & 7);
    const int a_kh  = (lane >> 4) * 8;
    const int b_nr  = (lane >> 4) * 8 + (lane & 7);
    const int b_kh  = ((lane >> 3) & 1) * 8;

    for (int it = 0; it < KITERS; ++it) {
        if (it + 1 < KITERS) load_stage(it + 1, (it + 1) & 1);
        else cp_commit();
        cp_wait1();
        __syncthreads();

        const uint32_t Ao = sb + (uint32_t)(it & 1) * 32768u;
        const uint32_t Bo = Ao + 16384u;

        #pragma unroll
        for (int ks = 0; ks < 4; ++ks) {
            uint32_t a[2][4];
            #pragma unroll
            for (int mt = 0; mt < 2; ++mt) {
                const int row = wm * 32 + mt * 16 + a_row;
                const int kc  = ks * 16 + a_kh;
                ldsm_x4(a[mt][0], a[mt][1], a[mt][2], a[mt][3],
                        Ao + SWZ((uint32_t)(row * 128 + kc * 2)));
            }
            uint32_t b[8][2];
            #pragma unroll
            for (int np = 0; np < 4; ++np) {
                const int nr = wn * 64 + np * 16 + b_nr;
                const int kc = ks * 16 + b_kh;
                ldsm_x4(b[np * 2][0], b[np * 2][1], b[np * 2 + 1][0], b[np * 2 + 1][1],
                        Bo + SWZ((uint32_t)(nr * 128 + kc * 2)));
            }
            #pragma unroll
            for (int mt = 0; mt < 2; ++mt)
                #pragma unroll
                for (int nt = 0; nt < 8; ++nt)
                    mma16816(acc[mt][nt], a[mt], b[nt]);
        }
        __syncthreads();
    }

    if (OUT_EPI) {
        #pragma unroll
        for (int mt = 0; mt < 2; ++mt) {
            const int r0 = rowg0 + wm * 32 + mt * 16 + (lane >> 2);
            #pragma unroll
            for (int nt = 0; nt < 8; ++nt) {
                const int c = ncol0 + wn * 64 + nt * 8 + (lane & 3) * 2;
                float2 v0 = make_float2(acc[mt][nt][0], acc[mt][nt][1]);
                float2 v1 = make_float2(acc[mt][nt][2], acc[mt][nt][3]);
                const float2 bo = *(const float2*)(bias + c);
                const float2 x0 = *(const float2*)(xres + (size_t)r0 * DIM + c);
                const float2 x1 = *(const float2*)(xres + (size_t)(r0 + 8) * DIM + c);
                v0.x += bo.x + x0.x; v0.y += bo.y + x0.y;
                v1.x += bo.x + x1.x; v1.y += bo.y + x1.y;
                *(float2*)(C + (size_t)r0 * DIM + c) = v0;
                *(float2*)(C + (size_t)(r0 + 8) * DIM + c) = v1;
            }
        }
    } else {
        __nv_bfloat16* dst = (blockIdx.x == 0) ? g_q : (blockIdx.x == 1) ? g_k : g_v;
        #pragma unroll
        for (int mt = 0; mt < 2; ++mt) {
            const int r0 = rowg0 + wm * 32 + mt * 16 + (lane >> 2);
            #pragma unroll
            for (int nt = 0; nt < 8; ++nt) {
                const int c = wn * 64 + nt * 8 + (lane & 3) * 2;
                *(__nv_bfloat162*)(dst + (size_t)r0 * HID + c) =
                    __float22bfloat162_rn(make_float2(acc[mt][nt][0], acc[mt][nt][1]));
                *(__nv_bfloat162*)(dst + (size_t)(r0 + 8) * HID + c) =
                    __float22bfloat162_rn(make_float2(acc[mt][nt][2], acc[mt][nt][3]));
            }
        }
    }
}

#define GEMM_SMEM 65536   // 2 stages x 32 KB

// grid (3, 256): q/k/v = xn @ wqkvT^T   (2 blocks/SM)
__global__ __launch_bounds__(256, 2) void k_qkv_mma() {
    extern __shared__ __align__(1024) char smem[];
    gemm_body<DIM, DIM, 16, false>(g_xn, g_wqkvT, nullptr, nullptr, nullptr, smem);
}
// grid (8, 256): out = q @ Wb_b^T + b_out + x
__global__ __launch_bounds__(256, 2) void k_out_mma(const float* __restrict__ x,
                                                    const float* __restrict__ b_out,
                                                    float* __restrict__ out) {
    extern __shared__ __align__(1024) char smem[];
    const int batch = blockIdx.y >> 5;
    gemm_body<HID, HID, 2, true>(g_q, g_wbT + (size_t)batch * DIM * HID,
                                 out, b_out, x, smem);
}

// ---------------------------------------------------------------------------
// K0: weight prep (transpose + bf16)
// ---------------------------------------------------------------------------
__global__ __launch_bounds__(256) void k_prep(const float* __restrict__ wqkv) {
    const int idx = blockIdx.x * 256 + threadIdx.x;
    if (idx < 384 * DIM) {
        const int n = idx >> 10, k = idx & 1023;
        g_wqkvT[idx] = __float2bfloat16(wqkv[k * 384 + n]);
    }
}

// ---------------------------------------------------------------------------
// K1: LayerNorm -> bf16
// ---------------------------------------------------------------------------
__global__ __launch_bounds__(256) void k_ln(const float* __restrict__ x,
                                            const float* __restrict__ gamma,
                                            const float* __restrict__ beta) {
    const int row = blockIdx.x;
    const int tid = threadIdx.x;
    const float4 f = ((const float4*)(x + (size_t)row * DIM))[tid];

    float s  = f.x + f.y + f.z + f.w;
    float s2 = fmaf(f.x, f.x, fmaf(f.y, f.y, fmaf(f.z, f.z, f.w * f.w)));
    #pragma unroll
    for (int off = 16; off > 0; off >>= 1) {
        s  += __shfl_xor_sync(0xffffffffu, s,  off);
        s2 += __shfl_xor_sync(0xffffffffu, s2, off);
    }
    __shared__ float red[16];
    const int wid = tid >> 5, lane = tid & 31;
    if (lane == 0) { red[wid] = s; red[8 + wid] = s2; }
    __syncthreads();
    float ts = 0.f, ts2 = 0.f;
    #pragma unroll
    for (int w = 0; w < 8; ++w) { ts += red[w]; ts2 += red[8 + w]; }

    const float mean = ts * (1.0f / DIM);
    const float var  = ts2 * (1.0f / DIM) - mean * mean;
    const float rstd = rsqrtf(var + EPS);

    const float4 g  = ((const float4*)gamma)[tid];
    const float4 be = ((const float4*)beta)[tid];
    __nv_bfloat162 p0, p1;
    p0.x = __float2bfloat16((f.x - mean) * rstd * g.x + be.x);
    p0.y = __float2bfloat16((f.y - mean) * rstd * g.y + be.y);
    p1.x = __float2bfloat16((f.z - mean) * rstd * g.z + be.z);
    p1.y = __float2bfloat16((f.w - mean) * rstd * g.w + be.w);
    __nv_bfloat162* o = (__nv_bfloat162*)(g_xn + (size_t)row * DIM);
    o[tid * 2 + 0] = p0;
    o[tid * 2 + 1] = p1;
}

// ---------------------------------------------------------------------------
// K3: ctx partials via HMMA.
// pctx[chunk,b,h,d,e] = sum_{n in chunk} exp(k)[n, h*32+d] * v[n, h*32+e]
// Tiles: exp(k), v as [128 n][128 col] bf16, 256B rows, CSWZ swizzle.
// A = expk^T, B = v^T via ldmatrix.x4.trans. Warp w: head w>>1, e-half w&1.
// grid (32, 8), 256 threads, dyn smem 66560 B.
// ---------------------------------------------------------------------------
#define CT_KS   0u
#define CT_VS   32768u
#define CT_RED  65536u
#define CT_SMEM 66560

__global__ __launch_bounds__(256, 2) void k_ctx_mma() {
    extern __shared__ __align__(1024) char smem[];
    const uint32_t sb = smem_to_u32(smem);
    const int chunk = blockIdx.x, b = blockIdx.y;
    const int tid = threadIdx.x, lane = tid & 31, wid = tid >> 5;

    const int rbase = b * SEQ + chunk * 128;

    // Fill: k -> exp(k) bf16, v raw copy; both swizzled.
    #pragma unroll
    for (int p = 0; p < 8; ++p) {
        const int idx = tid + p * 256;
        const int r = idx >> 4, c = idx & 15;          // c = 16B chunk
        const size_t go = (size_t)(rbase + r) * HID + c * 8;
        const uint4 kq = *(const uint4*)(g_k + go);
        const uint32_t kw[4] = {kq.x, kq.y, kq.z, kq.w};
        uint32_t ko[4];
        #pragma unroll
        for (int i = 0; i < 4; ++i) {
            const float2 f = __bfloat1622float2(*(const __nv_bfloat162*)&kw[i]);
            const __nv_bfloat162 e2 =
                __float22bfloat162_rn(make_float2(__expf(f.x), __expf(f.y)));
            ko[i] = *(const uint32_t*)&e2;
        }
        const uint32_t o = CSWZ((uint32_t)(r * 256 + c * 16));
        *(uint4*)(smem + CT_KS + o) = make_uint4(ko[0], ko[1], ko[2], ko[3]);
        *(uint4*)(smem + CT_VS + o) = *(const uint4*)(g_v + go);
    }
    __syncthreads();

    // pS: column sums of exp(k) (two-phase scalar reduce)
    {
        float* red = (float*)(smem + CT_RED);
        const int d = tid & 127, half = tid >> 7;
        float s = 0.f;
        #pragma unroll 4
        for (int r = half * 64; r < half * 64 + 64; ++r)
            s += __bfloat162float(*(const __nv_bfloat16*)
                     (smem + CT_KS + CSWZ((uint32_t)(r * 256 + d * 2))));
        red[half * 128 + d] = s;
    }
    __syncthreads();
    if (tid < 128)
        g_pS[chunk * (BATCH * HID) + b * HID + tid] =
            ((float*)(smem + CT_RED))[tid] + ((float*)(smem + CT_RED))[128 + tid];

    // MMA: warp w -> head h = w>>1, e-half eh = (w&1)*16.
    const int h  = wid >> 1;
    const int eh = (wid & 1) * 16;

    // A (trans): tile (mh,kh): src rows n0+kh*8+(l&7), col d0+mh*8
    const int a_n  = ((lane >> 4) * 8) + (lane & 7);
    const int a_d0 = h * 32 + ((lane >> 3) & 1) * 8;
    // B (trans): tile order {(e0,n0),(e0,n8),(e8,n0),(e8,n8)}
    const int b_n  = (((lane >> 3) & 1) * 8) + (lane & 7);
    const int b_e  = h * 32 + eh + (lane >> 4) * 8;

    float acc[2][2][4];
    #pragma unroll
    for (int mt = 0; mt < 2; ++mt)
        #pragma unroll
        for (int ng = 0; ng < 2; ++ng)
            #pragma unroll
            for (int i = 0; i < 4; ++i) acc[mt][ng][i] = 0.f;

    #pragma unroll
    for (int kt = 0; kt < 8; ++kt) {
        const int n0 = kt * 16;
        uint32_t a[2][4];
        #pragma unroll
        for (int mt = 0; mt < 2; ++mt)
            ldsm_x4_t(a[mt][0], a[mt][1], a[mt][2], a[mt][3],
                      sb + CT_KS + CSWZ((uint32_t)((n0 + a_n) * 256
                                                   + (a_d0 + mt * 16) * 2)));
        uint32_t bb[2][2];
        ldsm_x4_t(bb[0][0], bb[0][1], bb[1][0], bb[1][1],
                  sb + CT_VS + CSWZ((uint32_t)((n0 + b_n) * 256 + b_e * 2)));
        #pragma unroll
        for (int mt = 0; mt < 2; ++mt)
            #pragma unroll
            for (int ng = 0; ng < 2; ++ng)
                mma16816(acc[mt][ng], a[mt], bb[ng]);
    }

    // Store partials: C rows = d, cols = e
    const size_t ob = (size_t)chunk * 32768 + (size_t)b * 4096 + (size_t)h * 1024;
    #pragma unroll
    for (int mt = 0; mt < 2; ++mt) {
        const int d0 = mt * 16 + (lane >> 2);
        #pragma unroll
        for (int ng = 0; ng < 2; ++ng) {
            const int e = eh + ng * 8 + (lane & 3) * 2;
            *(float2*)(g_pctx + ob + (size_t)d0 * 32 + e) =
                make_float2(acc[mt][ng][0], acc[mt][ng][1]);
            *(float2*)(g_pctx + ob + (size_t)(d0 + 8) * 32 + e) =
                make_float2(acc[mt][ng][2], acc[mt][ng][3]);
        }
    }
}

// ---------------------------------------------------------------------------
// K4: reduce partials (grid 128 x 256)
// ---------------------------------------------------------------------------
__global__ __launch_bounds__(256) void k_ctx_reduce() {
    const int o  = blockIdx.x * 256 + threadIdx.x;
    const int bi = o >> 12;
    const int hd = (o >> 5) & 127;
    float s = 0.f, S = 0.f;
    #pragma unroll
    for (int c = 0; c < NCHUNK; ++c) {
        s += g_pctx[(size_t)c * 32768 + o];
        S += g_pS[c * (BATCH * HID) + bi * HID + hd];
    }
    g_ctx[o] = s * SCALE / S;
}

// ---------------------------------------------------------------------------
// K5: Wb_b = Ctx_b @ w_out  -> bf16 K-major [b][c][j]
// ---------------------------------------------------------------------------
__global__ __launch_bounds__(256) void k_wb(const float* __restrict__ wout) {
    __shared__ float ctx_s[4096];
    __shared__ float w_s[128][128];

    const int tid = threadIdx.x, lane = tid & 31;
    const int b = blockIdx.x >> 3;
    const int c0 = (blockIdx.x & 7) * 128;

    #pragma unroll
    for (int i = 0; i < 16; ++i)
        ctx_s[i * 256 + tid] = g_ctx[b * 4096 + i * 256 + tid];
    #pragma unroll
    for (int p = 0; p < 16; ++p) {
        const int idx = tid + p * 256;
        const int r = idx >> 5, c4 = idx & 31;
        *(float4*)&w_s[r][c4 * 4] = *(const float4*)(wout + r * DIM + c0 + c4 * 4);
    }
    __syncthreads();

    const int h = (tid >> 5) & 3;
    const int j = h * 32 + lane;
    const int cg = tid >> 7;

    float cv[32];
    #pragma unroll
    for (int e = 0; e < 32; ++e) cv[e] = ctx_s[h * 1024 + lane * 32 + e];

    for (int cc = 0; cc < 64; ++cc) {
        const int c = cg * 64 + cc;
        float a = 0.f;
        #pragma unroll
        for (int e = 0; e < 32; ++e)
            a = fmaf(cv[e], w_s[h * 32 + e][c], a);
        g_wbT[((size_t)b * DIM + c0 + c) * HID + j] = __float2bfloat16(a);
    }
}

// ---------------------------------------------------------------------------
extern "C" void kernel_launch(void* const* d_in, const int* in_sizes, int n_in,
                              void* d_out, int out_size) {
    const float* x     = (const float*)d_in[0];
    const float* gamma = (const float*)d_in[1];
    const float* beta  = (const float*)d_in[2];
    const float* wqkv  = (const float*)d_in[3];
    const float* wout  = (const float*)d_in[4];
    const float* bout  = (const float*)d_in[5];
    float* out = (float*)d_out;

    cudaFuncSetAttribute(k_qkv_mma, cudaFuncAttributeMaxDynamicSharedMemorySize, GEMM_SMEM);
    cudaFuncSetAttribute(k_out_mma, cudaFuncAttributeMaxDynamicSharedMemorySize, GEMM_SMEM);
    cudaFuncSetAttribute(k_ctx_mma, cudaFuncAttributeMaxDynamicSharedMemorySize, CT_SMEM);

    k_prep<<<1536, 256>>>(wqkv);
    k_ln<<<ROWS, 256>>>(x, gamma, beta);
    k_qkv_mma<<<dim3(3, 256), 256, GEMM_SMEM>>>();
    k_ctx_mma<<<dim3(NCHUNK, BATCH), 256, CT_SMEM>>>();
    k_ctx_reduce<<<128, 256>>>();
    k_wb<<<64, 256>>>(wout);
    k_out_mma<<<dim3(8, 256), 256, GEMM_SMEM>>>(x, bout, out);
}